// round 8
// baseline (speedup 1.0000x reference)
#include <cuda_runtime.h>

static constexpr int NV = 50000;
static constexpr int NE = 800000;

// ---------------- static device scratch (no allocations allowed) ----------------
__device__ float  g_z  [(size_t)NV * 128];
__device__ float  g_agg[(size_t)NV * 128];
__device__ float  g_h1 [(size_t)NV * 128];
__device__ float  g_h2 [(size_t)NV * 128];
__device__ float  g_inv[NV];
__device__ int    g_degI[NV];
__device__ int    g_rowoff[NV + 1];
__device__ int    g_cursor[NV];
__device__ int    g_col[NE];
__device__ int    g_src[NE];
__device__ int    g_dst[NE];
__device__ int    g_is64;
__device__ __align__(16) float2 g_wp[6][64 * 128]; // [slot][pair*128 + k] = (W[2p][k], W[2p+1][k])

// ---------------- f32x2 helpers ----------------
__device__ __forceinline__ void fma2(unsigned long long& d, unsigned long long a, unsigned long long b) {
    asm("fma.rn.f32x2 %0, %1, %2, %0;" : "+l"(d) : "l"(a), "l"(b));
}
__device__ __forceinline__ unsigned long long dup2(float a) {
    unsigned long long r;
    asm("mov.b64 %0, {%1, %1};" : "=l"(r) : "f"(a));
    return r;
}
__device__ __forceinline__ float2 unpk(unsigned long long v) {
    float2 r;
    asm("mov.b64 {%0, %1}, %2;" : "=f"(r.x), "=f"(r.y) : "l"(v));
    return r;
}

// ---------------- edge dtype detection + decode ----------------
__global__ void flag_init_kernel() {
    if (blockIdx.x == 0 && threadIdx.x == 0) g_is64 = 1;
}

// Read only the FIRST NE 8-byte words: safe whether the buffer holds
// 2*NE int32 (= NE int64-words total) or 2*NE int64 (= 2*NE words).
__global__ void detect_kernel(const long long* __restrict__ p) {
    int i = blockIdx.x * blockDim.x + threadIdx.x;
    if (i < NE) {
        long long v = p[i];
        if (v < 0 || v >= NV) g_is64 = 0;   // racing writes all write 0: benign
    }
}

__global__ void zero_deg_kernel() {
    int i = blockIdx.x * blockDim.x + threadIdx.x;
    if (i < NV) g_degI[i] = 0;
}

// decode src/dst under detected dtype + fused degree histogram
__global__ void decode_kernel(const void* __restrict__ p) {
    int e = blockIdx.x * blockDim.x + threadIdx.x;
    if (e >= NE) return;
    int s, d;
    if (g_is64) {
        const long long* q = (const long long*)p;
        s = (int)q[e];
        d = (int)q[NE + e];
    } else {
        const int* q = (const int*)p;
        s = q[e];
        d = q[NE + e];
    }
    g_src[e] = s;
    g_dst[e] = d;
    atomicAdd(&g_degI[d], 1);
}

// single-block exclusive scan over degrees -> rowoff/cursor, plus inv_deg
__global__ void scan_kernel() {
    __shared__ int wsum[32];
    __shared__ int carry;
    int tid = threadIdx.x;
    if (tid == 0) carry = 0;
    __syncthreads();
    for (int base = 0; base < NV + 1; base += 1024) {
        int i = base + tid;
        int v = (i < NV) ? g_degI[i] : 0;
        int x = v;
        #pragma unroll
        for (int o = 1; o < 32; o <<= 1) {
            int y = __shfl_up_sync(0xffffffffu, x, o);
            if ((tid & 31) >= o) x += y;
        }
        if ((tid & 31) == 31) wsum[tid >> 5] = x;
        __syncthreads();
        if (tid < 32) {
            int w = wsum[tid];
            #pragma unroll
            for (int o = 1; o < 32; o <<= 1) {
                int y = __shfl_up_sync(0xffffffffu, w, o);
                if (tid >= o) w += y;
            }
            wsum[tid] = w;
        }
        __syncthreads();
        int incl = x + ((tid >= 32) ? wsum[(tid >> 5) - 1] : 0) + carry;
        int excl = incl - v;
        if (i < NV) {
            g_rowoff[i] = excl;
            g_cursor[i] = excl;
            g_inv[i]    = 1.0f / fmaxf((float)v, 1.0f);
        } else if (i == NV) {
            g_rowoff[NV] = excl;
        }
        __syncthreads();
        if (tid == 1023) carry = incl;
        __syncthreads();
    }
}

__global__ void fill_kernel() {
    int e = blockIdx.x * blockDim.x + threadIdx.x;
    if (e < NE) {
        int p = atomicAdd(&g_cursor[g_dst[e]], 1);
        g_col[p] = g_src[e];
    }
}

// ---------------- weight packing: W[dout][128] -> float2 over adjacent out-cols ----------------
__global__ void pack_kernel(const float* __restrict__ W, int dout, int slot) {
    int n = (dout / 2) * 128;
    int idx = blockIdx.x * blockDim.x + threadIdx.x;
    if (idx < n) {
        int jp = idx >> 7, k = idx & 127;
        g_wp[slot][idx] = make_float2(W[(2 * jp) * 128 + k], W[(2 * jp + 1) * 128 + k]);
    }
}

// ---------------- SpMM: mean-gather, one warp per dst node, no atomics ----------------
template <int D>
__global__ void spmm_kernel() {
    int w    = (blockIdx.x * blockDim.x + threadIdx.x) >> 5;
    int lane = threadIdx.x & 31;
    if (w >= NV) return;
    int s = g_rowoff[w], e = g_rowoff[w + 1];
    float iv = g_inv[w];
    const float* z = g_z;
    if (D == 128) {
        float4 a0 = make_float4(0, 0, 0, 0), a1 = make_float4(0, 0, 0, 0);
        int j = s;
        for (; j + 1 < e; j += 2) {
            int c0 = g_col[j], c1 = g_col[j + 1];
            float4 v0 = *(const float4*)&z[(size_t)c0 * 128 + lane * 4];
            float4 v1 = *(const float4*)&z[(size_t)c1 * 128 + lane * 4];
            a0.x += v0.x; a0.y += v0.y; a0.z += v0.z; a0.w += v0.w;
            a1.x += v1.x; a1.y += v1.y; a1.z += v1.z; a1.w += v1.w;
        }
        if (j < e) {
            float4 v0 = *(const float4*)&z[(size_t)g_col[j] * 128 + lane * 4];
            a0.x += v0.x; a0.y += v0.y; a0.z += v0.z; a0.w += v0.w;
        }
        float4 r;
        r.x = (a0.x + a1.x) * iv; r.y = (a0.y + a1.y) * iv;
        r.z = (a0.z + a1.z) * iv; r.w = (a0.w + a1.w) * iv;
        *(float4*)&g_agg[(size_t)w * 128 + lane * 4] = r;
    } else {
        float2 a0 = make_float2(0, 0), a1 = make_float2(0, 0);
        int j = s;
        for (; j + 1 < e; j += 2) {
            int c0 = g_col[j], c1 = g_col[j + 1];
            float2 v0 = *(const float2*)&z[(size_t)c0 * 64 + lane * 2];
            float2 v1 = *(const float2*)&z[(size_t)c1 * 64 + lane * 2];
            a0.x += v0.x; a0.y += v0.y;
            a1.x += v1.x; a1.y += v1.y;
        }
        if (j < e) {
            float2 v0 = *(const float2*)&z[(size_t)g_col[j] * 64 + lane * 2];
            a0.x += v0.x; a0.y += v0.y;
        }
        float2 r;
        r.x = (a0.x + a1.x) * iv; r.y = (a0.y + a1.y) * iv;
        *(float2*)&g_agg[(size_t)w * 64 + lane * 2] = r;
    }
}

// ---------------- GEMM: O[N][DOUT] = A[N][128] @ W^T (+ agg + bias, relu) ----------------
// 128-row x 64-col tile, K in 4 chunks of 32. 256 threads: 16 row-groups x 16 col-groups,
// each thread 8 rows x 2 col-pairs, f32x2 accumulation. Static smem ~25 KB (no opt-in).
template <int DOUT, bool EPI>
__global__ __launch_bounds__(256)
void gemm_kernel(const float* __restrict__ Xin, int in_sel, int wslot,
                 const float* __restrict__ bias, float* __restrict__ Oparam,
                 int out_sel, int relu)
{
    __shared__ __align__(16) float4 sA[8 * 129];   // [k4][row], pad 129 rows
    __shared__ __align__(16) float2 sW[32 * 34];   // [pair][k], pad stride 34 (even -> 16B-aligned rows)

    const float* A = (in_sel == 0) ? Xin : (in_sel == 1 ? g_h1 : g_h2);
    float*       O = (out_sel == 3) ? Oparam
                   : (out_sel == 0 ? g_z : (out_sel == 1 ? g_h1 : g_h2));

    int tid = threadIdx.x;
    int rg = tid >> 4, cg = tid & 15;
    int row0 = blockIdx.x * 128;
    int cp0  = blockIdx.y * 32;      // col-pair base
    int rb   = rg * 8;

    unsigned long long acc[8][2];
    #pragma unroll
    for (int r = 0; r < 8; r++) { acc[r][0] = 0ull; acc[r][1] = 0ull; }

    const float2* wsrc = g_wp[wslot];

    for (int c = 0; c < 4; ++c) {
        // stage W chunk: 32 pairs x 32 k (512 float4)
        for (int i = tid; i < 512; i += 256) {
            int pair = i >> 4, kk2 = i & 15;
            float4 v = *(const float4*)&wsrc[(cp0 + pair) * 128 + c * 32 + kk2 * 2];
            *(float4*)&sW[pair * 34 + kk2 * 2] = v;
        }
        // stage A chunk: 128 rows x 32 k (1024 float4), k4-fastest for coalescing
        for (int i = tid; i < 1024; i += 256) {
            int k4 = i & 7, row = i >> 3;
            int gr = row0 + row;
            float4 v = make_float4(0, 0, 0, 0);
            if (gr < NV) v = *(const float4*)&A[(size_t)gr * 128 + c * 32 + k4 * 4];
            sA[k4 * 129 + row] = v;
        }
        __syncthreads();

        #pragma unroll
        for (int k4 = 0; k4 < 8; ++k4) {
            const ulonglong2* wp0 = (const ulonglong2*)&sW[cg * 34 + k4 * 4];
            const ulonglong2* wp1 = (const ulonglong2*)&sW[(cg + 16) * 34 + k4 * 4];
            ulonglong2 w00 = wp0[0], w01 = wp0[1];
            ulonglong2 w10 = wp1[0], w11 = wp1[1];
            #pragma unroll
            for (int r = 0; r < 8; ++r) {
                float4 av = sA[k4 * 129 + rb + r];
                unsigned long long ax = dup2(av.x), ay = dup2(av.y),
                                   az = dup2(av.z), aw = dup2(av.w);
                fma2(acc[r][0], ax, w00.x); fma2(acc[r][1], ax, w10.x);
                fma2(acc[r][0], ay, w00.y); fma2(acc[r][1], ay, w10.y);
                fma2(acc[r][0], az, w01.x); fma2(acc[r][1], az, w11.x);
                fma2(acc[r][0], aw, w01.y); fma2(acc[r][1], aw, w11.y);
            }
        }
        __syncthreads();
    }

    #pragma unroll
    for (int r = 0; r < 8; ++r) {
        int gr = row0 + rb + r;
        if (gr >= NV) continue;
        #pragma unroll
        for (int p = 0; p < 2; ++p) {
            int gp = cp0 + cg + 16 * p;
            float2 v = unpk(acc[r][p]);
            if (EPI) {
                float2 ag = *(const float2*)&g_agg[(size_t)gr * DOUT + 2 * gp];
                v.x += ag.x + bias[2 * gp];
                v.y += ag.y + bias[2 * gp + 1];
                if (relu) { v.x = fmaxf(v.x, 0.f); v.y = fmaxf(v.y, 0.f); }
            }
            *(float2*)&O[(size_t)gr * DOUT + 2 * gp] = v;
        }
    }
}

// ---------------- launch: kernel launches ONLY ----------------
extern "C" void kernel_launch(void* const* d_in, const int* in_sizes, int n_in,
                              void* d_out, int out_size)
{
    const float* x   = (const float*)d_in[0];
    const void*  ei  = d_in[1];                 // int32 or int64: detected at runtime
    const float* Wl0 = (const float*)d_in[2];
    const float* bl0 = (const float*)d_in[3];
    const float* Wr0 = (const float*)d_in[4];
    const float* Wl1 = (const float*)d_in[5];
    const float* bl1 = (const float*)d_in[6];
    const float* Wr1 = (const float*)d_in[7];
    const float* Wl2 = (const float*)d_in[8];
    const float* bl2 = (const float*)d_in[9];
    const float* Wr2 = (const float*)d_in[10];
    float*       out = (float*)d_out;

    // edge dtype detection + CSR build (counting sort) — deterministic, rebuilt each call
    flag_init_kernel<<<1, 32>>>();
    detect_kernel<<<(NE + 255) / 256, 256>>>((const long long*)ei);
    zero_deg_kernel<<<(NV + 255) / 256, 256>>>();
    decode_kernel<<<(NE + 255) / 256, 256>>>(ei);
    scan_kernel<<<1, 1024>>>();
    fill_kernel<<<(NE + 255) / 256, 256>>>();

    // weight packing
    pack_kernel<<<32, 256>>>(Wl0, 128, 0);
    pack_kernel<<<32, 256>>>(Wr0, 128, 1);
    pack_kernel<<<32, 256>>>(Wl1, 128, 2);
    pack_kernel<<<32, 256>>>(Wr1, 128, 3);
    pack_kernel<<<16, 256>>>(Wl2, 64, 4);
    pack_kernel<<<16, 256>>>(Wr2, 64, 5);

    const dim3 G128((NV + 127) / 128, 2);  // 391 x 2
    const dim3 G64 ((NV + 127) / 128, 1);  // 391 x 1
    const int  SB = (NV * 32 + 255) / 256; // 6250: one warp per node

    // layer 0: h1 = relu( mean_nbr(x) @ Wl0^T + bl0 + x @ Wr0^T )   [agg reordered after GEMM]
    gemm_kernel<128, false><<<G128, 256>>>(x, 0, 0, bl0, nullptr, 0, 0); // z = x @ Wl0^T
    spmm_kernel<128><<<SB, 256>>>();                                     // agg = mean(z)
    gemm_kernel<128, true ><<<G128, 256>>>(x, 0, 1, bl0, nullptr, 1, 1); // h1 = relu(agg + bl0 + x@Wr0^T)

    // layer 1
    gemm_kernel<128, false><<<G128, 256>>>(x, 1, 2, bl1, nullptr, 0, 0); // z = h1 @ Wl1^T
    spmm_kernel<128><<<SB, 256>>>();
    gemm_kernel<128, true ><<<G128, 256>>>(x, 1, 3, bl1, nullptr, 2, 1); // h2

    // layer 2 (no relu), aggregation in 64-dim output space
    gemm_kernel<64, false><<<G64, 256>>>(x, 2, 4, bl2, nullptr, 0, 0);   // z = h2 @ Wl2^T (64-dim)
    spmm_kernel<64><<<SB, 256>>>();
    gemm_kernel<64, true ><<<G64, 256>>>(x, 2, 5, bl2, out, 3, 0);       // out
}